// round 1
// baseline (speedup 1.0000x reference)
#include <cuda_runtime.h>
#include <cstdint>

// Static config (Fp8Padding num_gemms=8, align=16)
// M_SPLITS       = {4091, 8177, 2045, 4093, 6133, 1021, 4085, 8189}
// PADDED_SPLITS  = {4096, 8192, 2048, 4096, 6144, 1024, 4096, 8192}
// HIDDEN = 2048 floats = 512 float4 per row
// TOTAL_IN rows  = 37834, TOTAL_OUT rows = 37888

#define HIDDEN4     512          // float4 per row
#define TOTAL_OUT4  (37888 * HIDDEN4)   // 19,398,656 float4

__constant__ int c_out_start[8] = {0, 4096, 12288, 14336, 18432, 24576, 25600, 29696};
__constant__ int c_in_start [8] = {0, 4091, 12268, 14313, 18406, 24539, 25560, 29645};
__constant__ int c_m        [8] = {4091, 8177, 2045, 4093, 6133, 1021, 4085, 8189};

__global__ void __launch_bounds__(256) fp8_padding_kernel(
    const float4* __restrict__ in, float4* __restrict__ out)
{
    int idx = blockIdx.x * 256 + threadIdx.x;   // < TOTAL_OUT4, grid sized exactly
    int row = idx >> 9;                          // output row
    int col = idx & (HIDDEN4 - 1);               // float4 column within row

    // Branch-free segment lookup over the 8 static padded-row boundaries.
    int seg = (row >= 4096)  + (row >= 12288) + (row >= 14336) + (row >= 18432)
            + (row >= 24576) + (row >= 25600) + (row >= 29696);

    int local = row - c_out_start[seg];
    float4 v;
    if (local < c_m[seg]) {
        int src_row = c_in_start[seg] + local;
        v = in[(long long)src_row * HIDDEN4 + col];
    } else {
        v = make_float4(0.f, 0.f, 0.f, 0.f);     // alignment pad row
    }
    out[idx] = v;
}

extern "C" void kernel_launch(void* const* d_in, const int* in_sizes, int n_in,
                              void* d_out, int out_size)
{
    const float4* in  = (const float4*)d_in[0];
    float4*       out = (float4*)d_out;
    // TOTAL_OUT4 = 19,398,656 = 75,776 * 256 exactly
    fp8_padding_kernel<<<TOTAL_OUT4 / 256, 256>>>(in, out);
}

// round 2
// speedup vs baseline: 1.0258x; 1.0258x over previous
#include <cuda_runtime.h>
#include <cstdint>

// Static config (Fp8Padding num_gemms=8, align=16)
// M_SPLITS       = {4091, 8177, 2045, 4093, 6133, 1021, 4085, 8189}
// PADDED_SPLITS  = {4096, 8192, 2048, 4096, 6144, 1024, 4096, 8192}
// HIDDEN = 2048 floats = 512 float4 per row

#define HIDDEN4     512                      // float4 per row
#define TOTAL_OUT4  (37888 * HIDDEN4)        // 19,398,656 float4
#define VPT         4                        // float4 per thread
#define TPB         256
#define CHUNK       (TPB * VPT)              // 1024 float4 per block

__constant__ int c_out_start[8] = {0, 4096, 12288, 14336, 18432, 24576, 25600, 29696};
__constant__ int c_in_start [8] = {0, 4091, 12268, 14313, 18406, 24539, 25560, 29645};
__constant__ int c_m        [8] = {4091, 8177, 2045, 4093, 6133, 1021, 4085, 8189};

__global__ void __launch_bounds__(TPB) fp8_padding_kernel(
    const float4* __restrict__ in, float4* __restrict__ out)
{
    int base = blockIdx.x * CHUNK + threadIdx.x;

    float4 v[VPT];

    // Front-batched independent loads (MLP_p1 = 4). Pad rows predicated off.
    #pragma unroll
    for (int k = 0; k < VPT; k++) {
        int idx = base + k * TPB;
        int row = idx >> 9;
        int col = idx & (HIDDEN4 - 1);

        // Branch-free segment lookup over the 8 static padded-row boundaries.
        int seg = (row >= 4096)  + (row >= 12288) + (row >= 14336) + (row >= 18432)
                + (row >= 24576) + (row >= 25600) + (row >= 29696);

        int local = row - c_out_start[seg];
        v[k] = make_float4(0.f, 0.f, 0.f, 0.f);
        if (local < c_m[seg]) {                       // predicated LDG.128
            int src_row = c_in_start[seg] + local;
            v[k] = __ldg(&in[(long long)src_row * HIDDEN4 + col]);
        }
    }

    #pragma unroll
    for (int k = 0; k < VPT; k++) {
        out[base + k * TPB] = v[k];
    }
}

extern "C" void kernel_launch(void* const* d_in, const int* in_sizes, int n_in,
                              void* d_out, int out_size)
{
    const float4* in  = (const float4*)d_in[0];
    float4*       out = (float4*)d_out;
    // TOTAL_OUT4 = 19,398,656 = 18,944 * 1024 exactly
    fp8_padding_kernel<<<TOTAL_OUT4 / CHUNK, TPB>>>(in, out);
}